// round 7
// baseline (speedup 1.0000x reference)
#include <cuda_runtime.h>

#define NCTA   128
#define TPB    256
#define PP     1024
#define DD     32
#define RS     1032
#define MAXIT  30
#define EPSV   0.1f
#define LN2F   0.69314718055994530942f
#define ALPHA  14.4269504088896340736f   /* 1/(eps*ln2) */
#define THRESH 0.1f

typedef unsigned long long u64;

__device__ unsigned g_arr[NCTA];           // monotonic arrival counters (4B apart)
__device__ float    g_b2[4096];            // B per (batch, col)
__device__ float2   g_cp[NCTA * PP];       // per-CTA column partials (m, s)
__device__ float    g_errp[MAXIT * NCTA];  // per-iter per-CTA |dA| sums
__device__ double   g_costp[NCTA];         // per-CTA cost partials

struct Smem {
    float  K2[32 * RS];        // 132096 B
    float  bb[PP];
    float  lnu2[PP];
    float  colShift[PP];
    float  ystage[256 * DD];
    double redd[TPB];
    float2 cmb[8][32];
    float  A2s[32];
    float  lmu2s[32];
    float  rowShift[32];
    float  errAcc;
    float  errTot;
    float  Sx, Sy;
};

__device__ __forceinline__ float ex2f(float x){ float r; asm("ex2.approx.ftz.f32 %0, %1;" : "=f"(r) : "f"(x)); return r; }
__device__ __forceinline__ float lg2f(float x){ float r; asm("lg2.approx.f32 %0, %1;" : "=f"(r) : "f"(x)); return r; }
__device__ __forceinline__ u64 pk2(float lo, float hi){ u64 r; asm("mov.b64 %0, {%1, %2};" : "=l"(r) : "f"(lo), "f"(hi)); return r; }
__device__ __forceinline__ void upk2(u64 v, float& lo, float& hi){ asm("mov.b64 {%0, %1}, %2;" : "=f"(lo), "=f"(hi) : "l"(v)); }
__device__ __forceinline__ void fma2(u64& d, u64 a, u64 b){ asm("fma.rn.f32x2 %0, %1, %2, %0;" : "+l"(d) : "l"(a), "l"(b)); }
__device__ __forceinline__ u64 add2(u64 a, u64 b){ u64 r; asm("add.rn.f32x2 %0, %1, %2;" : "=l"(r) : "l"(a), "l"(b)); return r; }

__device__ __forceinline__ void st_rel(unsigned* p, unsigned v) {
    asm volatile("st.release.gpu.global.u32 [%0], %1;" :: "l"(p), "r"(v) : "memory");
}
__device__ __forceinline__ unsigned ld_acq(const unsigned* p) {
    unsigned v;
    asm volatile("ld.acquire.gpu.global.u32 %0, [%1];" : "=r"(v) : "l"(p) : "memory");
    return v;
}

// batch-local barrier: 32 CTAs, warp 0 polls all 32 flags in one coalesced load
__device__ __forceinline__ void bbar(unsigned target, int nb, int bid) {
    __syncthreads();
    if (threadIdx.x == 0) st_rel(&g_arr[bid], target);
    if (threadIdx.x < 32) {
        unsigned* p = &g_arr[nb * 32 + threadIdx.x];
        unsigned v = ld_acq(p);
        while (__any_sync(0xffffffffu, (int)(v - target) < 0)) v = ld_acq(p);
    }
    __syncthreads();
}

// global barrier: 128 flags, 4 coalesced lines
__device__ __forceinline__ void gbarAll(unsigned target, int bid) {
    __syncthreads();
    if (threadIdx.x == 0) st_rel(&g_arr[bid], target);
    if (threadIdx.x < 32) {
        unsigned v0, v1, v2, v3;
        do {
            v0 = ld_acq(&g_arr[threadIdx.x]);
            v1 = ld_acq(&g_arr[threadIdx.x + 32]);
            v2 = ld_acq(&g_arr[threadIdx.x + 64]);
            v3 = ld_acq(&g_arr[threadIdx.x + 96]);
        } while (__any_sync(0xffffffffu,
            (((int)(v0 - target)) < 0) || (((int)(v1 - target)) < 0) ||
            (((int)(v2 - target)) < 0) || (((int)(v3 - target)) < 0)));
    }
    __syncthreads();
}

__global__ void __launch_bounds__(TPB, 1)
sinkhorn_kernel(const float* __restrict__ gx, const float* __restrict__ gy,
                const float* __restrict__ gxw, const float* __restrict__ gyw,
                float* __restrict__ gout)
{
    extern __shared__ __align__(16) char smraw[];
    Smem* S = reinterpret_cast<Smem*>(smraw);

    const int tid  = threadIdx.x;
    const int lane = tid & 31;
    const int warp = tid >> 5;       // 0..7
    const int bid  = blockIdx.x;
    const int nb   = bid >> 5;
    const int sub  = bid & 31;
    const int r0   = sub * 32;

    unsigned tgt = ld_acq(&g_arr[bid]);   // own counter: lockstep base

    // global weight sums (redundant per CTA, deterministic)
    {
        float px = 0.f, py = 0.f;
        for (int k = tid; k < 4096; k += TPB) { px += gxw[k]; py += gyw[k]; }
        S->redd[tid] = (double)px; __syncthreads();
        for (int s = TPB/2; s > 0; s >>= 1) { if (tid < s) S->redd[tid] += S->redd[tid+s]; __syncthreads(); }
        if (tid == 0) S->Sx = (float)S->redd[0];
        __syncthreads();
        S->redd[tid] = (double)py; __syncthreads();
        for (int s = TPB/2; s > 0; s >>= 1) { if (tid < s) S->redd[tid] += S->redd[tid+s]; __syncthreads(); }
        if (tid == 0) { S->Sy = (float)S->redd[0]; S->errAcc = 0.f; }
        __syncthreads();
    }

    if (tid < 32) {
        S->lmu2s[tid] = lg2f(gxw[nb * PP + r0 + tid] / S->Sx + 1e-8f);
        S->A2s[tid]   = 0.f;
    }
    for (int c = tid; c < PP; c += TPB)
        S->lnu2[c] = lg2f(gyw[nb * PP + c] / S->Sy + 1e-8f);

    // ---- build K2 = -C/(eps*ln2) in SMEM ----
    const float* ybase = gy + (size_t)nb * PP * DD;
    for (int c = tid; c < PP; c += TPB) {
        const float4* yc = (const float4*)(ybase + c * DD);
        float s = 0.f;
#pragma unroll
        for (int q = 0; q < 8; q++) { float4 v = yc[q]; s += v.x*v.x + v.y*v.y + v.z*v.z + v.w*v.w; }
        S->bb[c] = s * ALPHA;   // temp: ALPHA*|y|^2
    }
    float xv[32];
    {
        const float4* xr = (const float4*)(gx + (size_t)(nb * PP + r0 + lane) * DD);
#pragma unroll
        for (int q = 0; q < 8; q++) {
            float4 v = xr[q];
            xv[4*q] = v.x; xv[4*q+1] = v.y; xv[4*q+2] = v.z; xv[4*q+3] = v.w;
        }
    }
    float x2 = 0.f;
#pragma unroll
    for (int d = 0; d < 32; d++) x2 += xv[d] * xv[d];
    const float cx = ALPHA * x2;
    u64 xp[16];
#pragma unroll
    for (int q = 0; q < 16; q++) xp[q] = pk2(xv[2*q], xv[2*q+1]);
    __syncthreads();

    for (int chunk = 0; chunk < 4; chunk++) {
        const int j0 = chunk * 256;
        const float4* ysrc = (const float4*)(ybase + j0 * DD);
        float4* yst = (float4*)S->ystage;
#pragma unroll
        for (int q = 0; q < 8; q++) yst[tid + 256 * q] = ysrc[tid + 256 * q];
        __syncthreads();
#pragma unroll 4
        for (int m = 0; m < 32; m++) {
            const int jj = warp + 8 * m;
            const ulonglong2* yp = (const ulonglong2*)(S->ystage + jj * DD);
            u64 acc[4] = {0ull, 0ull, 0ull, 0ull};
#pragma unroll
            for (int q = 0; q < 8; q++) {
                ulonglong2 w = yp[q];
                fma2(acc[(2*q)   & 3], xp[2*q],     w.x);
                fma2(acc[(2*q+1) & 3], xp[2*q + 1], w.y);
            }
            u64 st = add2(add2(acc[0], acc[1]), add2(acc[2], acc[3]));
            float lo, hi; upk2(st, lo, hi);
            float dot = lo + hi;
            S->K2[lane * RS + j0 + jj] = fmaf(dot, 2.f * ALPHA, -(cx + S->bb[j0 + jj]));
        }
        __syncthreads();
    }

    // row maxes (iter-0 shift; exact since B=0 at iter 0)
#pragma unroll
    for (int k = 0; k < 4; k++) {
        const int r = warp * 4 + k;
        const float4* kr = (const float4*)(S->K2 + r * RS);
        float m = -1e30f;
#pragma unroll
        for (int q = 0; q < 8; q++) {
            float4 a = kr[lane + 32 * q];
            m = fmaxf(m, fmaxf(fmaxf(a.x, a.y), fmaxf(a.z, a.w)));
        }
#pragma unroll
        for (int o = 16; o; o >>= 1) m = fmaxf(m, __shfl_xor_sync(0xffffffffu, m, o));
        if (lane == 0) S->rowShift[r] = m;
    }
#pragma unroll
    for (int cc = 0; cc < 4; cc++) S->bb[tid + 256 * cc] = 0.f;
    __syncthreads();

    const int c0 = 2 * tid, c1 = 2 * tid + 1, c2 = 2 * tid + 512, c3 = 2 * tid + 513;

    // ================= Sinkhorn iterations =================
    int iter = 0;
    for (;;) {
        // ---------- row (u) update: shift = prev row LSE; 4 rows share bb loads ----------
        {
            const float4* b4 = (const float4*)S->bb;
            const float4* kr0 = (const float4*)(S->K2 + (warp * 4 + 0) * RS);
            const float4* kr1 = (const float4*)(S->K2 + (warp * 4 + 1) * RS);
            const float4* kr2 = (const float4*)(S->K2 + (warp * 4 + 2) * RS);
            const float4* kr3 = (const float4*)(S->K2 + (warp * 4 + 3) * RS);
            const float m0 = S->rowShift[warp * 4 + 0];
            const float m1 = S->rowShift[warp * 4 + 1];
            const float m2 = S->rowShift[warp * 4 + 2];
            const float m3 = S->rowShift[warp * 4 + 3];
            float s0 = 0.f, s1 = 0.f, s2 = 0.f, s3 = 0.f;
#pragma unroll
            for (int q = 0; q < 8; q++) {
                const int ix = lane + 32 * q;
                float4 b = b4[ix];
                float4 a0 = kr0[ix], a1 = kr1[ix], a2 = kr2[ix], a3 = kr3[ix];
                s0 += ex2f(a0.x + b.x - m0) + ex2f(a0.y + b.y - m0) + ex2f(a0.z + b.z - m0) + ex2f(a0.w + b.w - m0);
                s1 += ex2f(a1.x + b.x - m1) + ex2f(a1.y + b.y - m1) + ex2f(a1.z + b.z - m1) + ex2f(a1.w + b.w - m1);
                s2 += ex2f(a2.x + b.x - m2) + ex2f(a2.y + b.y - m2) + ex2f(a2.z + b.z - m2) + ex2f(a2.w + b.w - m2);
                s3 += ex2f(a3.x + b.x - m3) + ex2f(a3.y + b.y - m3) + ex2f(a3.z + b.z - m3) + ex2f(a3.w + b.w - m3);
            }
#pragma unroll
            for (int o = 16; o; o >>= 1) {
                s0 += __shfl_xor_sync(0xffffffffu, s0, o);
                s1 += __shfl_xor_sync(0xffffffffu, s1, o);
                s2 += __shfl_xor_sync(0xffffffffu, s2, o);
                s3 += __shfl_xor_sync(0xffffffffu, s3, o);
            }
            if (lane == 0) {
                float lse0 = m0 + lg2f(s0), lse1 = m1 + lg2f(s1);
                float lse2 = m2 + lg2f(s2), lse3 = m3 + lg2f(s3);
                const int r = warp * 4;
                float a0 = S->lmu2s[r+0] - lse0, a1 = S->lmu2s[r+1] - lse1;
                float a2 = S->lmu2s[r+2] - lse2, a3 = S->lmu2s[r+3] - lse3;
                float de = fabsf(a0 - S->A2s[r+0]) + fabsf(a1 - S->A2s[r+1])
                         + fabsf(a2 - S->A2s[r+2]) + fabsf(a3 - S->A2s[r+3]);
                atomicAdd(&S->errAcc, de);
                S->A2s[r+0] = a0; S->A2s[r+1] = a1; S->A2s[r+2] = a2; S->A2s[r+3] = a3;
                S->rowShift[r+0] = lse0; S->rowShift[r+1] = lse1;
                S->rowShift[r+2] = lse2; S->rowShift[r+3] = lse3;
            }
        }
        __syncthreads();
        if (tid == 0) {
            __stcg(&g_errp[iter * NCTA + bid], S->errAcc);
            S->errAcc = 0.f;
        }

        // ---------- column partials over own 32 rows ----------
        if (iter == 0) {
            float m0=-1e30f, m1=-1e30f, m2=-1e30f, m3=-1e30f;
#pragma unroll
            for (int r = 0; r < 32; r++) {
                const float ar = S->A2s[r];
                const float* kr = S->K2 + r * RS;
                float2 ka = *(const float2*)(kr + c0);
                float2 kb = *(const float2*)(kr + c2);
                m0 = fmaxf(m0, ka.x + ar);
                m1 = fmaxf(m1, ka.y + ar);
                m2 = fmaxf(m2, kb.x + ar);
                m3 = fmaxf(m3, kb.y + ar);
            }
            S->colShift[c0] = m0; S->colShift[c1] = m1;
            S->colShift[c2] = m2; S->colShift[c3] = m3;
        }
        {
            const float mc0 = S->colShift[c0], mc1 = S->colShift[c1];
            const float mc2 = S->colShift[c2], mc3 = S->colShift[c3];
            float s0 = 0.f, s1 = 0.f, s2 = 0.f, s3 = 0.f;
#pragma unroll
            for (int r = 0; r < 32; r++) {
                const float ar = S->A2s[r];
                const float* kr = S->K2 + r * RS;
                float2 ka = *(const float2*)(kr + c0);
                float2 kb = *(const float2*)(kr + c2);
                s0 += ex2f(ka.x + (ar - mc0));
                s1 += ex2f(ka.y + (ar - mc1));
                s2 += ex2f(kb.x + (ar - mc2));
                s3 += ex2f(kb.y + (ar - mc3));
            }
            *(float4*)(&g_cp[bid * PP + c0]) = make_float4(mc0, s0, mc1, s1);
            *(float4*)(&g_cp[bid * PP + c2]) = make_float4(mc2, s2, mc3, s3);
            S->colShift[c0] = mc0 + lg2f(s0);
            S->colShift[c1] = mc1 + lg2f(s1);
            S->colShift[c2] = mc2 + lg2f(s2);
            S->colShift[c3] = mc3 + lg2f(s3);
        }
        bbar(++tgt, nb, bid);

        // ---------- combine own 32 columns (tree) -> B ----------
        {
            const float2* cpb = g_cp + (size_t)(nb * 32) * PP + (sub * 32 + lane);
            float2 p = __ldcg(cpb + warp * PP);
#pragma unroll
            for (int k = 1; k < 4; k++) {
                float2 q = __ldcg(cpb + (warp + 8 * k) * PP);
                float mn = fmaxf(p.x, q.x);
                p.y = p.y * ex2f(p.x - mn) + q.y * ex2f(q.x - mn);
                p.x = mn;
            }
            S->cmb[warp][lane] = p;
        }
        __syncthreads();
        if (warp == 0) {
            float2 p = S->cmb[0][lane];
#pragma unroll
            for (int w = 1; w < 8; w++) {
                float2 q = S->cmb[w][lane];
                float mn = fmaxf(p.x, q.x);
                p.y = p.y * ex2f(p.x - mn) + q.y * ex2f(q.x - mn);
                p.x = mn;
            }
            float B = S->lnu2[sub * 32 + lane] - (p.x + lg2f(p.y));
            __stcg(&g_b2[nb * PP + sub * 32 + lane], B);
        }
        gbarAll(++tgt, bid);

        // ---------- tail: reload B, global err check ----------
        ((float4*)S->bb)[tid] = __ldcg(((const float4*)(g_b2 + nb * PP)) + tid);
        if (warp == 0) {
            const float* ep = g_errp + iter * NCTA;
            float e = __ldcg(ep + lane) + __ldcg(ep + lane + 32)
                    + __ldcg(ep + lane + 64) + __ldcg(ep + lane + 96);
#pragma unroll
            for (int o = 16; o; o >>= 1) e += __shfl_xor_sync(0xffffffffu, e, o);
            if (lane == 0) S->errTot = e;
        }
        __syncthreads();

        iter++;
        if (iter >= MAXIT) break;
        if (S->errTot * (EPSV * LN2F * 0.25f) < THRESH) break;
    }

    // ---- final cost: cost_n = -eps*ln2 * sum 2^(K2+A+B) * K2 ----
    {
        const float bc0 = S->bb[c0], bc1 = S->bb[c1];
        const float bc2 = S->bb[c2], bc3 = S->bb[c3];
        float acc = 0.f;
#pragma unroll 8
        for (int r = 0; r < 32; r++) {
            const float ar = S->A2s[r];
            const float* kr = S->K2 + r * RS;
            float2 ka = *(const float2*)(kr + c0);
            float2 kb = *(const float2*)(kr + c2);
            acc = fmaf(ex2f(ka.x + ar + bc0), ka.x, acc);
            acc = fmaf(ex2f(ka.y + ar + bc1), ka.y, acc);
            acc = fmaf(ex2f(kb.x + ar + bc2), kb.x, acc);
            acc = fmaf(ex2f(kb.y + ar + bc3), kb.y, acc);
        }
        S->redd[tid] = (double)acc; __syncthreads();
        for (int s = TPB/2; s > 0; s >>= 1) { if (tid < s) S->redd[tid] += S->redd[tid+s]; __syncthreads(); }
        if (tid == 0) __stcg(&g_costp[bid], S->redd[0]);
    }
    gbarAll(++tgt, bid);
    if (sub == 0 && warp == 0) {
        double cv = __ldcg(&g_costp[nb * 32 + lane]);
#pragma unroll
        for (int o = 16; o; o >>= 1) {
            double ov = __shfl_xor_sync(0xffffffffu, cv, o);
            cv += ov;
        }
        if (lane == 0)
            gout[nb] = (float)(-(double)EPSV * (double)LN2F * cv);
    }
}

extern "C" void kernel_launch(void* const* d_in, const int* in_sizes, int n_in,
                              void* d_out, int out_size) {
    const float* x  = (const float*)d_in[0];
    const float* y  = (const float*)d_in[1];
    const float* xw = (const float*)d_in[2];
    const float* yw = (const float*)d_in[3];
    float* out = (float*)d_out;
    size_t smem = sizeof(Smem);
    cudaFuncSetAttribute(sinkhorn_kernel, cudaFuncAttributeMaxDynamicSharedMemorySize, (int)smem);
    sinkhorn_kernel<<<NCTA, TPB, smem>>>(x, y, xw, yw, out);
}

// round 8
// speedup vs baseline: 1.3351x; 1.3351x over previous
#include <cuda_runtime.h>

#define NCTA   128
#define TPB    256
#define PP     1024
#define DD     32
#define RS     1032
#define MAXIT  30
#define EPSV   0.1f
#define LN2F   0.69314718055994530942f
#define ALPHA  14.4269504088896340736f   /* 1/(eps*ln2) */
#define THRESH 0.1f

typedef unsigned long long u64;

__device__ unsigned          g_cnt[4 * 32];    // per-batch arrival counter (padded)
__device__ volatile unsigned g_genb[4 * 32];   // per-batch generation flag (padded)
__device__ float    g_b2[4096];                // B per (batch, col)
__device__ float2   g_cp[NCTA * PP];           // per-CTA column partials (m, s)
__device__ float    g_errpart[NCTA];           // per-CTA row-err partials
__device__ float    g_errv[4 * MAXIT];         // published per-batch err per iter
__device__ volatile unsigned g_errseq[4 * 8];  // per-batch publish sequence (padded)
__device__ double   g_costp[NCTA];             // per-CTA cost partials

struct Smem {
    float  K2[32 * RS];        // 132096 B
    float  bb[PP];
    float  lnu2[PP];
    float  colShift[PP];
    float  ystage[256 * DD];
    double redd[TPB];
    float2 cmb[8][32];
    float  A2s[32];
    float  lmu2s[32];
    float  rowShift[32];
    float  errv4[4];
    float  errAcc;
    float  Sx, Sy;
};

__device__ __forceinline__ float ex2f(float x){ float r; asm("ex2.approx.ftz.f32 %0, %1;" : "=f"(r) : "f"(x)); return r; }
__device__ __forceinline__ float lg2f(float x){ float r; asm("lg2.approx.f32 %0, %1;" : "=f"(r) : "f"(x)); return r; }
__device__ __forceinline__ u64 pk2(float lo, float hi){ u64 r; asm("mov.b64 %0, {%1, %2};" : "=l"(r) : "f"(lo), "f"(hi)); return r; }
__device__ __forceinline__ void upk2(u64 v, float& lo, float& hi){ asm("mov.b64 {%0, %1}, %2;" : "=f"(lo), "=f"(hi) : "l"(v)); }
__device__ __forceinline__ void fma2(u64& d, u64 a, u64 b){ asm("fma.rn.f32x2 %0, %1, %2, %0;" : "+l"(d) : "l"(a), "l"(b)); }
__device__ __forceinline__ u64 add2(u64 a, u64 b){ u64 r; asm("add.rn.f32x2 %0, %1, %2;" : "=l"(r) : "l"(a), "l"(b)); return r; }

// Batch-local barrier: single atomic counter + single gen flag (R3-style, per batch).
__device__ __forceinline__ void bbar(unsigned target, int nb) {
    __syncthreads();
    if (threadIdx.x == 0) {
        __threadfence();
        if (atomicAdd(&g_cnt[nb * 32], 1u) == 31u) {
            g_cnt[nb * 32] = 0;
            __threadfence();
            g_genb[nb * 32] = target;
        } else {
            while (g_genb[nb * 32] != target) { }
            __threadfence();
        }
    }
    __syncthreads();
}

__global__ void __launch_bounds__(TPB, 1)
sinkhorn_kernel(const float* __restrict__ gx, const float* __restrict__ gy,
                const float* __restrict__ gxw, const float* __restrict__ gyw,
                float* __restrict__ gout)
{
    extern __shared__ __align__(16) char smraw[];
    Smem* S = reinterpret_cast<Smem*>(smraw);

    const int tid  = threadIdx.x;
    const int lane = tid & 31;
    const int warp = tid >> 5;       // 0..7
    const int bid  = blockIdx.x;
    const int nb   = bid >> 5;
    const int sub  = bid & 31;
    const int r0   = sub * 32;

    unsigned tgt   = g_genb[nb * 32];    // quiescent at launch start
    const unsigned ebase = g_errseq[nb * 8];

    // global weight sums (redundant per CTA, deterministic)
    {
        float px = 0.f, py = 0.f;
        for (int k = tid; k < 4096; k += TPB) { px += gxw[k]; py += gyw[k]; }
        S->redd[tid] = (double)px; __syncthreads();
        for (int s = TPB/2; s > 0; s >>= 1) { if (tid < s) S->redd[tid] += S->redd[tid+s]; __syncthreads(); }
        if (tid == 0) S->Sx = (float)S->redd[0];
        __syncthreads();
        S->redd[tid] = (double)py; __syncthreads();
        for (int s = TPB/2; s > 0; s >>= 1) { if (tid < s) S->redd[tid] += S->redd[tid+s]; __syncthreads(); }
        if (tid == 0) { S->Sy = (float)S->redd[0]; S->errAcc = 0.f; }
        __syncthreads();
    }

    if (tid < 32) {
        S->lmu2s[tid] = lg2f(gxw[nb * PP + r0 + tid] / S->Sx + 1e-8f);
        S->A2s[tid]   = 0.f;
    }
    for (int c = tid; c < PP; c += TPB)
        S->lnu2[c] = lg2f(gyw[nb * PP + c] / S->Sy + 1e-8f);

    // ---- build K2 = -C/(eps*ln2) in SMEM ----
    const float* ybase = gy + (size_t)nb * PP * DD;
    for (int c = tid; c < PP; c += TPB) {
        const float4* yc = (const float4*)(ybase + c * DD);
        float s = 0.f;
#pragma unroll
        for (int q = 0; q < 8; q++) { float4 v = yc[q]; s += v.x*v.x + v.y*v.y + v.z*v.z + v.w*v.w; }
        S->bb[c] = s * ALPHA;   // temp: ALPHA*|y|^2
    }
    float xv[32];
    {
        const float4* xr = (const float4*)(gx + (size_t)(nb * PP + r0 + lane) * DD);
#pragma unroll
        for (int q = 0; q < 8; q++) {
            float4 v = xr[q];
            xv[4*q] = v.x; xv[4*q+1] = v.y; xv[4*q+2] = v.z; xv[4*q+3] = v.w;
        }
    }
    float x2 = 0.f;
#pragma unroll
    for (int d = 0; d < 32; d++) x2 += xv[d] * xv[d];
    const float cx = ALPHA * x2;
    u64 xp[16];
#pragma unroll
    for (int q = 0; q < 16; q++) xp[q] = pk2(xv[2*q], xv[2*q+1]);
    __syncthreads();

    for (int chunk = 0; chunk < 4; chunk++) {
        const int j0 = chunk * 256;
        const float4* ysrc = (const float4*)(ybase + j0 * DD);
        float4* yst = (float4*)S->ystage;
#pragma unroll
        for (int q = 0; q < 8; q++) yst[tid + 256 * q] = ysrc[tid + 256 * q];
        __syncthreads();
#pragma unroll 4
        for (int m = 0; m < 32; m++) {
            const int jj = warp + 8 * m;
            const ulonglong2* yp = (const ulonglong2*)(S->ystage + jj * DD);
            u64 acc[4] = {0ull, 0ull, 0ull, 0ull};
#pragma unroll
            for (int q = 0; q < 8; q++) {
                ulonglong2 w = yp[q];
                fma2(acc[(2*q)   & 3], xp[2*q],     w.x);
                fma2(acc[(2*q+1) & 3], xp[2*q + 1], w.y);
            }
            u64 st = add2(add2(acc[0], acc[1]), add2(acc[2], acc[3]));
            float lo, hi; upk2(st, lo, hi);
            float dot = lo + hi;
            S->K2[lane * RS + j0 + jj] = fmaf(dot, 2.f * ALPHA, -(cx + S->bb[j0 + jj]));
        }
        __syncthreads();
    }

    // row maxes (iter-0 shift; exact since B=0 at iter 0)
#pragma unroll
    for (int k = 0; k < 4; k++) {
        const int r = warp * 4 + k;
        const float4* kr = (const float4*)(S->K2 + r * RS);
        float m = -1e30f;
#pragma unroll
        for (int q = 0; q < 8; q++) {
            float4 a = kr[lane + 32 * q];
            m = fmaxf(m, fmaxf(fmaxf(a.x, a.y), fmaxf(a.z, a.w)));
        }
#pragma unroll
        for (int o = 16; o; o >>= 1) m = fmaxf(m, __shfl_xor_sync(0xffffffffu, m, o));
        if (lane == 0) S->rowShift[r] = m;
    }
#pragma unroll
    for (int cc = 0; cc < 4; cc++) S->bb[tid + 256 * cc] = 0.f;
    __syncthreads();

    const int c0 = 2 * tid, c1 = 2 * tid + 1, c2 = 2 * tid + 512, c3 = 2 * tid + 513;

    // ================= Sinkhorn iterations =================
    int iter = 0;
    for (;;) {
        // ---------- row (u) update: shift = prev row LSE; 4 rows share bb loads ----------
        {
            const float4* b4 = (const float4*)S->bb;
            const float4* kr0 = (const float4*)(S->K2 + (warp * 4 + 0) * RS);
            const float4* kr1 = (const float4*)(S->K2 + (warp * 4 + 1) * RS);
            const float4* kr2 = (const float4*)(S->K2 + (warp * 4 + 2) * RS);
            const float4* kr3 = (const float4*)(S->K2 + (warp * 4 + 3) * RS);
            const float m0 = S->rowShift[warp * 4 + 0];
            const float m1 = S->rowShift[warp * 4 + 1];
            const float m2 = S->rowShift[warp * 4 + 2];
            const float m3 = S->rowShift[warp * 4 + 3];
            float s0 = 0.f, s1 = 0.f, s2 = 0.f, s3 = 0.f;
#pragma unroll
            for (int q = 0; q < 8; q++) {
                const int ix = lane + 32 * q;
                float4 b = b4[ix];
                float4 a0 = kr0[ix], a1 = kr1[ix], a2 = kr2[ix], a3 = kr3[ix];
                s0 += ex2f(a0.x + b.x - m0) + ex2f(a0.y + b.y - m0) + ex2f(a0.z + b.z - m0) + ex2f(a0.w + b.w - m0);
                s1 += ex2f(a1.x + b.x - m1) + ex2f(a1.y + b.y - m1) + ex2f(a1.z + b.z - m1) + ex2f(a1.w + b.w - m1);
                s2 += ex2f(a2.x + b.x - m2) + ex2f(a2.y + b.y - m2) + ex2f(a2.z + b.z - m2) + ex2f(a2.w + b.w - m2);
                s3 += ex2f(a3.x + b.x - m3) + ex2f(a3.y + b.y - m3) + ex2f(a3.z + b.z - m3) + ex2f(a3.w + b.w - m3);
            }
#pragma unroll
            for (int o = 16; o; o >>= 1) {
                s0 += __shfl_xor_sync(0xffffffffu, s0, o);
                s1 += __shfl_xor_sync(0xffffffffu, s1, o);
                s2 += __shfl_xor_sync(0xffffffffu, s2, o);
                s3 += __shfl_xor_sync(0xffffffffu, s3, o);
            }
            if (lane == 0) {
                float lse0 = m0 + lg2f(s0), lse1 = m1 + lg2f(s1);
                float lse2 = m2 + lg2f(s2), lse3 = m3 + lg2f(s3);
                const int r = warp * 4;
                float a0 = S->lmu2s[r+0] - lse0, a1 = S->lmu2s[r+1] - lse1;
                float a2 = S->lmu2s[r+2] - lse2, a3 = S->lmu2s[r+3] - lse3;
                float de = fabsf(a0 - S->A2s[r+0]) + fabsf(a1 - S->A2s[r+1])
                         + fabsf(a2 - S->A2s[r+2]) + fabsf(a3 - S->A2s[r+3]);
                atomicAdd(&S->errAcc, de);
                S->A2s[r+0] = a0; S->A2s[r+1] = a1; S->A2s[r+2] = a2; S->A2s[r+3] = a3;
                S->rowShift[r+0] = lse0; S->rowShift[r+1] = lse1;
                S->rowShift[r+2] = lse2; S->rowShift[r+3] = lse3;
            }
        }
        __syncthreads();
        if (tid == 0) {
            __stcg(&g_errpart[bid], S->errAcc);
            S->errAcc = 0.f;
        }

        // ---------- column partials over own 32 rows ----------
        if (iter == 0) {
            float m0=-1e30f, m1=-1e30f, m2=-1e30f, m3=-1e30f;
#pragma unroll
            for (int r = 0; r < 32; r++) {
                const float ar = S->A2s[r];
                const float* kr = S->K2 + r * RS;
                float2 ka = *(const float2*)(kr + c0);
                float2 kb = *(const float2*)(kr + c2);
                m0 = fmaxf(m0, ka.x + ar);
                m1 = fmaxf(m1, ka.y + ar);
                m2 = fmaxf(m2, kb.x + ar);
                m3 = fmaxf(m3, kb.y + ar);
            }
            S->colShift[c0] = m0; S->colShift[c1] = m1;
            S->colShift[c2] = m2; S->colShift[c3] = m3;
        }
        {
            const float mc0 = S->colShift[c0], mc1 = S->colShift[c1];
            const float mc2 = S->colShift[c2], mc3 = S->colShift[c3];
            float s0 = 0.f, s1 = 0.f, s2 = 0.f, s3 = 0.f;
#pragma unroll
            for (int r = 0; r < 32; r++) {
                const float ar = S->A2s[r];
                const float* kr = S->K2 + r * RS;
                float2 ka = *(const float2*)(kr + c0);
                float2 kb = *(const float2*)(kr + c2);
                s0 += ex2f(ka.x + (ar - mc0));
                s1 += ex2f(ka.y + (ar - mc1));
                s2 += ex2f(kb.x + (ar - mc2));
                s3 += ex2f(kb.y + (ar - mc3));
            }
            *(float4*)(&g_cp[bid * PP + c0]) = make_float4(mc0, s0, mc1, s1);
            *(float4*)(&g_cp[bid * PP + c2]) = make_float4(mc2, s2, mc3, s3);
            S->colShift[c0] = mc0 + lg2f(s0);
            S->colShift[c1] = mc1 + lg2f(s1);
            S->colShift[c2] = mc2 + lg2f(s2);
            S->colShift[c3] = mc3 + lg2f(s3);
        }
        bbar(++tgt, nb);

        // ---------- combine own 32 columns (tree) -> B ----------
        {
            const float2* cpb = g_cp + (size_t)(nb * 32) * PP + (sub * 32 + lane);
            float2 p = __ldcg(cpb + warp * PP);
#pragma unroll
            for (int k = 1; k < 4; k++) {
                float2 q = __ldcg(cpb + (warp + 8 * k) * PP);
                float mn = fmaxf(p.x, q.x);
                p.y = p.y * ex2f(p.x - mn) + q.y * ex2f(q.x - mn);
                p.x = mn;
            }
            S->cmb[warp][lane] = p;
        }
        __syncthreads();
        if (warp == 0) {
            float2 p = S->cmb[0][lane];
#pragma unroll
            for (int w = 1; w < 8; w++) {
                float2 q = S->cmb[w][lane];
                float mn = fmaxf(p.x, q.x);
                p.y = p.y * ex2f(p.x - mn) + q.y * ex2f(q.x - mn);
                p.x = mn;
            }
            float B = S->lnu2[sub * 32 + lane] - (p.x + lg2f(p.y));
            __stcg(&g_b2[nb * PP + sub * 32 + lane], B);
        }
        // designated CTA publishes this batch's err (deterministic fixed-order reduce)
        if (sub == 0 && warp == 1) {
            float e = __ldcg(&g_errpart[nb * 32 + lane]);
#pragma unroll
            for (int o = 16; o; o >>= 1) e += __shfl_xor_sync(0xffffffffu, e, o);
            if (lane == 0) {
                __stcg(&g_errv[nb * MAXIT + iter], e);
                __threadfence();
                g_errseq[nb * 8] = ebase + (unsigned)iter + 1u;
            }
        }
        bbar(++tgt, nb);

        // ---------- tail: reload B; gather all-batch err; decide ----------
        float4 breg = __ldcg(((const float4*)(g_b2 + nb * PP)) + tid);
        if (tid < 4) {
            const unsigned want = ebase + (unsigned)iter + 1u;
            while ((int)(g_errseq[tid * 8] - want) < 0) { }
            __threadfence();
            S->errv4[tid] = __ldcg(&g_errv[tid * MAXIT + iter]);
        }
        ((float4*)S->bb)[tid] = breg;
        __syncthreads();
        float ev = ((S->errv4[0] + S->errv4[1]) + (S->errv4[2] + S->errv4[3]));

        iter++;
        if (iter >= MAXIT) break;
        if (ev * (EPSV * LN2F * 0.25f) < THRESH) break;
    }

    // ---- final cost: cost_n = -eps*ln2 * sum 2^(K2+A+B) * K2 ----
    {
        const float bc0 = S->bb[c0], bc1 = S->bb[c1];
        const float bc2 = S->bb[c2], bc3 = S->bb[c3];
        float acc = 0.f;
#pragma unroll 8
        for (int r = 0; r < 32; r++) {
            const float ar = S->A2s[r];
            const float* kr = S->K2 + r * RS;
            float2 ka = *(const float2*)(kr + c0);
            float2 kb = *(const float2*)(kr + c2);
            acc = fmaf(ex2f(ka.x + ar + bc0), ka.x, acc);
            acc = fmaf(ex2f(ka.y + ar + bc1), ka.y, acc);
            acc = fmaf(ex2f(kb.x + ar + bc2), kb.x, acc);
            acc = fmaf(ex2f(kb.y + ar + bc3), kb.y, acc);
        }
        S->redd[tid] = (double)acc; __syncthreads();
        for (int s = TPB/2; s > 0; s >>= 1) { if (tid < s) S->redd[tid] += S->redd[tid+s]; __syncthreads(); }
        if (tid == 0) __stcg(&g_costp[bid], S->redd[0]);
    }
    bbar(++tgt, nb);
    if (sub == 0 && warp == 0) {
        double cv = __ldcg(&g_costp[nb * 32 + lane]);
#pragma unroll
        for (int o = 16; o; o >>= 1)
            cv += __shfl_xor_sync(0xffffffffu, cv, o);
        if (lane == 0)
            gout[nb] = (float)(-(double)EPSV * (double)LN2F * cv);
    }
}

extern "C" void kernel_launch(void* const* d_in, const int* in_sizes, int n_in,
                              void* d_out, int out_size) {
    const float* x  = (const float*)d_in[0];
    const float* y  = (const float*)d_in[1];
    const float* xw = (const float*)d_in[2];
    const float* yw = (const float*)d_in[3];
    float* out = (float*)d_out;
    size_t smem = sizeof(Smem);
    cudaFuncSetAttribute(sinkhorn_kernel, cudaFuncAttributeMaxDynamicSharedMemorySize, (int)smem);
    sinkhorn_kernel<<<NCTA, TPB, smem>>>(x, y, xw, yw, out);
}